// round 1
// baseline (speedup 1.0000x reference)
#include <cuda_runtime.h>
#include <math.h>

// ConvolutionalCapsule with EM routing on GB300.
// One CTA per output spatial position (B*12*12 = 1152 CTAs), 256 threads.
// Votes [144,16,16] kept resident in shared memory (147KB).
// Thread t = o*16+p owns output-capsule o, pose element p for all EM math.
//
// Constants (from reference): KERNEL=3, STRIDE=1, I=16, O=16, ROUTINGS=3, EPS=1e-9
// B=8, H=W=14 -> H'=W'=12.

#define EPS 1e-9f
#define NPOS 1152      // 8*12*12
#define ICAP 144       // 9*16
#define OCAP 16
#define NPAIR 2304     // ICAP*OCAP
#define VOTES_F 36864  // ICAP*OCAP*16
#define SMEM_FLOATS (VOTES_F + NPAIR + ICAP)
#define SMEM_BYTES (SMEM_FLOATS * 4)

__global__ __launch_bounds__(256, 1)
void caps_em_kernel(const float* __restrict__ pose_in,   // [8,14,14,256]
                    const float* __restrict__ act_in,    // [8,14,14,16]
                    const float* __restrict__ w,         // [144,16,4,4]
                    const float* __restrict__ beta_v,    // [16]
                    const float* __restrict__ beta_a,    // [16]
                    float* __restrict__ out)             // pose [1152,16,16] ++ act [1152,16]
{
    extern __shared__ float sm[];
    float* votes = sm;                 // [144][16][16]
    float* rr    = sm + VOTES_F;       // [144][16]  (aliased: im2col patch during vote compute)
    float* acts  = rr + NPAIR;         // [144]
    float* patch = rr;                 // alias: [144][16] pose patch (2304 floats)

    const int n = blockIdx.x;
    const int x = n % 12;
    const int y = (n / 12) % 12;
    const int b = n / 144;
    const int t = threadIdx.x;
    const int o = t >> 4;
    const int p = t & 15;

    // ---- load im2col patch: 9 window positions ----
    #pragma unroll
    for (int kp = 0; kp < 9; ++kp) {
        const int ky = kp / 3, kx = kp % 3;
        const int base = (b * 14 + (y + ky)) * 14 + (x + kx);
        patch[kp * 256 + t] = pose_in[base * 256 + t];
        if (t < 16) acts[kp * 16 + t] = act_in[base * 16 + t];
    }
    __syncthreads();

    // ---- compute votes: votes[i,o] = pose4[i] (4x4) @ w[i,o] (4x4) ----
    for (int idx = t; idx < NPAIR; idx += 256) {
        const int i = idx >> 4;
        const float4* pw = (const float4*)(w + (size_t)idx * 16);
        const float4 w0 = pw[0], w1 = pw[1], w2 = pw[2], w3 = pw[3];
        const float* pr = patch + i * 16;   // broadcast across the 16 o-threads of same i
        float4* vout = (float4*)(votes + idx * 16);
        #pragma unroll
        for (int r = 0; r < 4; ++r) {
            const float a0 = pr[r * 4 + 0], a1 = pr[r * 4 + 1];
            const float a2 = pr[r * 4 + 2], a3 = pr[r * 4 + 3];
            float4 res;
            res.x = a0 * w0.x + a1 * w1.x + a2 * w2.x + a3 * w3.x;
            res.y = a0 * w0.y + a1 * w1.y + a2 * w2.y + a3 * w3.y;
            res.z = a0 * w0.z + a1 * w1.z + a2 * w2.z + a3 * w3.z;
            res.w = a0 * w0.w + a1 * w1.w + a2 * w2.w + a3 * w3.w;
            vout[r] = res;
        }
    }
    __syncthreads();   // votes done; patch region can now become rr

    // ---- init rr = 1/O ----
    for (int idx = t; idx < NPAIR; idx += 256)
        rr[idx] = 1.0f / 16.0f;
    __syncthreads();

    const float bv = beta_v[o];
    const float ba = beta_a[o];

    // ---- EM routing: 3 iterations, inv_temp = 1 + it ----
    for (int it = 0; it < 3; ++it) {
        const float inv_temp = 1.0f + (float)it;

        // M-step: thread (o,p) reduces over i
        float S0 = 0.f, S1 = 0.f, S2 = 0.f;
        #pragma unroll 4
        for (int i = 0; i < ICAP; ++i) {
            const float rp = rr[i * 16 + o] * acts[i];
            const float v  = votes[i * 256 + t];
            S0 += rp;
            S1 += rp * v;
            S2 += rp * v * v;
        }
        const float mean   = S1 / (S0 + EPS);
        const float varsum = fmaxf(S2 - 2.f * mean * S1 + mean * mean * S0, 0.f);
        const float stdv   = sqrtf(varsum / (S0 + EPS));
        const float lg     = logf(stdv + EPS);

        // sum of log(stdv+eps) over the 16 pose dims (16-lane butterfly)
        float L = lg;
        L += __shfl_xor_sync(0xffffffffu, L, 8);
        L += __shfl_xor_sync(0xffffffffu, L, 4);
        L += __shfl_xor_sync(0xffffffffu, L, 2);
        L += __shfl_xor_sync(0xffffffffu, L, 1);

        const float costsum = (16.f * bv + L) * S0;
        const float oact    = 1.f / (1.f + expf(-(inv_temp * (ba - costsum))));

        if (it == 2) {
            // final: write pose (= o_mean) and activation
            out[n * 256 + t] = mean;
            if (p == 0) out[NPOS * 256 + n * 16 + o] = oact;
        } else {
            // E-step: zz[i,o] = log(oact+eps) - sum_p (v-m)^2/(2s^2+eps) - sum_p log(s+eps)
            const float invd = 1.f / (2.f * stdv * stdv + EPS);
            const float lga  = logf(oact + EPS);
            #pragma unroll 4
            for (int i = 0; i < ICAP; ++i) {
                const float v = votes[i * 256 + t];
                const float d = v - mean;
                float term = d * d * invd;
                term += __shfl_xor_sync(0xffffffffu, term, 8);
                term += __shfl_xor_sync(0xffffffffu, term, 4);
                term += __shfl_xor_sync(0xffffffffu, term, 2);
                term += __shfl_xor_sync(0xffffffffu, term, 1);
                if (p == 0) rr[i * 16 + o] = lga - term - L;   // zz (own column, no hazard)
            }
            __syncthreads();

            // softmax over o per input capsule i
            if (t < ICAP) {
                float z[16];
                float mx = -3.4e38f;
                #pragma unroll
                for (int oo = 0; oo < 16; ++oo) {
                    z[oo] = rr[t * 16 + oo];
                    mx = fmaxf(mx, z[oo]);
                }
                float s = 0.f;
                #pragma unroll
                for (int oo = 0; oo < 16; ++oo) {
                    z[oo] = expf(z[oo] - mx);
                    s += z[oo];
                }
                const float inv = 1.f / s;
                #pragma unroll
                for (int oo = 0; oo < 16; ++oo)
                    rr[t * 16 + oo] = z[oo] * inv;
            }
            __syncthreads();
        }
    }
}

extern "C" void kernel_launch(void* const* d_in, const int* in_sizes, int n_in,
                              void* d_out, int out_size) {
    const float* pose_in = (const float*)d_in[0];
    const float* act_in  = (const float*)d_in[1];
    const float* w       = (const float*)d_in[2];
    const float* beta_v  = (const float*)d_in[3];
    const float* beta_a  = (const float*)d_in[4];
    float* out = (float*)d_out;

    cudaFuncSetAttribute(caps_em_kernel,
                         cudaFuncAttributeMaxDynamicSharedMemorySize, SMEM_BYTES);
    caps_em_kernel<<<NPOS, 256, SMEM_BYTES>>>(pose_in, act_in, w, beta_v, beta_a, out);
}

// round 2
// speedup vs baseline: 2.9771x; 2.9771x over previous
#include <cuda_runtime.h>
#include <math.h>

// ConvolutionalCapsule EM routing, R2: 512 threads/CTA, shuffle-free E-step,
// conflict-free rotated LDS.128 access, acts folded into rr.
//
// One CTA per output position (1152 CTAs). Votes [144,16,16] fp32 in smem.
// Thread layout: t = h*256 + o*16 + p  (h = I-split half for the M-step).
// E-step: thread handles pairs idx = t + 512k (oo = t&15 fixed), computing
// zz2[i,oo] = C[oo] - sum_p v*(v*a - 2b)  in base-2 log space.

#define EPS 1e-9f
#define LOG2E 1.4426950408889634f
#define NPOS 1152
#define ICAP 144
#define NPAIR 2304
#define VOTES_F 36864

// smem layout (floats)
#define OFF_RR    36864          // [144][16] rr (aliased: im2col pose patch)
#define OFF_ACTS  39168          // [144]
#define OFF_PC    39312          // [3][256] M-step partials from half h=1
#define OFF_A     40080          // [256] invd * log2e
#define OFF_B     40336          // [256] mean * invd * log2e
#define OFF_C     40592          // [16]
#define SMEM_FLOATS 40608
#define SMEM_BYTES (SMEM_FLOATS * 4)

__global__ __launch_bounds__(512, 1)
void caps_em_kernel(const float* __restrict__ pose_in,   // [8,14,14,256]
                    const float* __restrict__ act_in,    // [8,14,14,16]
                    const float* __restrict__ w,         // [144,16,4,4]
                    const float* __restrict__ beta_v,    // [16]
                    const float* __restrict__ beta_a,    // [16]
                    float* __restrict__ out)             // pose[1152,256] ++ act[1152,16]
{
    extern __shared__ float sm[];
    float* votes = sm;
    float* rr    = sm + OFF_RR;
    float* acts  = sm + OFF_ACTS;
    float* pc    = sm + OFF_PC;
    float* a_sm  = sm + OFF_A;
    float* b_sm  = sm + OFF_B;
    float* c_sm  = sm + OFF_C;

    const int n = blockIdx.x;
    const int x = n % 12;
    const int y = (n / 12) % 12;
    const int b = n / 144;
    const int t  = threadIdx.x;
    const int tt = t & 255;
    const int h  = t >> 8;
    const int o  = tt >> 4;
    const int p  = tt & 15;
    const int rot = ((t & 3) + ((t >> 2) & 1)) & 3;   // phase-conflict-free chunk rotation

    // ---- load im2col patch (aliased into rr) + acts ----
    for (int idx = t; idx < NPAIR; idx += 512) {
        const int kp = idx >> 8, c = idx & 255;
        const int base = (b * 14 + (y + kp / 3)) * 14 + (x + kp % 3);
        rr[idx] = pose_in[base * 256 + c];
    }
    if (t < ICAP) {
        const int kp = t >> 4;
        const int base = (b * 14 + (y + kp / 3)) * 14 + (x + kp % 3);
        acts[t] = act_in[base * 16 + (t & 15)];
    }
    __syncthreads();

    // ---- votes[i,o] = pose4[i] @ w[i,o], rotated row order for conflict-free STS.128 ----
    for (int idx = t; idx < NPAIR; idx += 512) {
        const int i = idx >> 4;
        const float4* pw = (const float4*)(w + (size_t)idx * 16);
        const float4 w0 = pw[0], w1 = pw[1], w2 = pw[2], w3 = pw[3];
        const float* pr = rr + i * 16;   // patch row (broadcast within warp)
        float4* vout = (float4*)(votes + idx * 16);
        #pragma unroll
        for (int rq = 0; rq < 4; ++rq) {
            const int r = (rq + rot) & 3;
            const float a0 = pr[r * 4 + 0], a1 = pr[r * 4 + 1];
            const float a2 = pr[r * 4 + 2], a3 = pr[r * 4 + 3];
            float4 res;
            res.x = a0 * w0.x + a1 * w1.x + a2 * w2.x + a3 * w3.x;
            res.y = a0 * w0.y + a1 * w1.y + a2 * w2.y + a3 * w3.y;
            res.z = a0 * w0.z + a1 * w1.z + a2 * w2.z + a3 * w3.z;
            res.w = a0 * w0.w + a1 * w1.w + a2 * w2.w + a3 * w3.w;
            vout[r] = res;
        }
    }
    __syncthreads();

    float bv = 0.f, ba = 0.f;
    if (t < 256) { bv = beta_v[o]; ba = beta_a[o]; }

    for (int it = 0; it < 3; ++it) {
        // ---- M-step partial reduction over this half's 72 input capsules ----
        float S0 = 0.f, S1 = 0.f, S2 = 0.f;
        const int i0 = h * 72;
        if (it == 0) {
            #pragma unroll 4
            for (int i = i0; i < i0 + 72; ++i) {
                const float rp = acts[i] * 0.0625f;
                const float v  = votes[i * 256 + tt];
                const float t1 = rp * v;
                S0 += rp; S1 += t1; S2 += t1 * v;
            }
        } else {
            #pragma unroll 4
            for (int i = i0; i < i0 + 72; ++i) {
                const float rp = rr[i * 16 + o];          // already *acts (folded in softmax)
                const float v  = votes[i * 256 + tt];
                const float t1 = rp * v;
                S0 += rp; S1 += t1; S2 += t1 * v;
            }
        }
        if (h) { pc[tt] = S0; pc[256 + tt] = S1; pc[512 + tt] = S2; }
        __syncthreads();

        if (t < 256) {
            S0 += pc[t]; S1 += pc[256 + t]; S2 += pc[512 + t];
            const float mean = S1 / (S0 + EPS);
            float varsum = S2 - 2.f * mean * S1 + mean * mean * S0;
            varsum = fmaxf(varsum, 0.f);
            const float stdv = sqrtf(varsum / (S0 + EPS));
            const float lg   = logf(stdv + EPS);
            const float invd = 1.f / (2.f * stdv * stdv + EPS);
            const float av   = invd * LOG2E;
            const float bco  = mean * av;

            // butterfly over 16 pose dims: L = sum lg ; MB = sum mean*bco
            float L = lg, MB = mean * bco;
            #pragma unroll
            for (int d = 8; d; d >>= 1) {
                L  += __shfl_xor_sync(0xffffffffu, L,  d);
                MB += __shfl_xor_sync(0xffffffffu, MB, d);
            }

            const float costsum = (16.f * bv + L) * S0;
            const float itemp = 1.f + (float)it;
            const float oact = 1.f / (1.f + expf(-(itemp * (ba - costsum))));

            if (it == 2) {
                out[n * 256 + t] = mean;
                if (p == 0) out[NPOS * 256 + n * 16 + o] = oact;
            } else {
                a_sm[t] = av;
                b_sm[t] = bco;
                if (p == 0) c_sm[o] = (logf(oact + EPS) - L) * LOG2E - MB;
            }
        }
        __syncthreads();
        if (it == 2) break;

        // ---- E-step: zz2[idx] = C[oo] - sum_p v*(v*a - 2b), no shuffles ----
        {
            const int oo = t & 15;
            float4 A4[4], B4[4];
            #pragma unroll
            for (int qq = 0; qq < 4; ++qq) {
                const int q = (qq + rot) & 3;
                A4[qq] = ((const float4*)a_sm)[(oo << 2) | q];
                float4 bb = ((const float4*)b_sm)[(oo << 2) | q];
                bb.x *= -2.f; bb.y *= -2.f; bb.z *= -2.f; bb.w *= -2.f;
                B4[qq] = bb;
            }
            const float C = c_sm[oo];

            #pragma unroll
            for (int k = 0; k < 4; ++k) {
                const int idx = t + 512 * k;
                float4 s4 = make_float4(0.f, 0.f, 0.f, 0.f);
                #pragma unroll
                for (int qq = 0; qq < 4; ++qq) {
                    const int q = (qq + rot) & 3;
                    const float4 v = ((const float4*)votes)[(idx << 2) | q];
                    float4 u;
                    u.x = fmaf(v.x, A4[qq].x, B4[qq].x);
                    u.y = fmaf(v.y, A4[qq].y, B4[qq].y);
                    u.z = fmaf(v.z, A4[qq].z, B4[qq].z);
                    u.w = fmaf(v.w, A4[qq].w, B4[qq].w);
                    s4.x = fmaf(v.x, u.x, s4.x);
                    s4.y = fmaf(v.y, u.y, s4.y);
                    s4.z = fmaf(v.z, u.z, s4.z);
                    s4.w = fmaf(v.w, u.w, s4.w);
                }
                rr[idx] = C - ((s4.x + s4.y) + (s4.z + s4.w));
            }
            if (t < 256) {                       // tail: pairs 2048..2303
                const int idx = t + 2048;
                float4 s4 = make_float4(0.f, 0.f, 0.f, 0.f);
                #pragma unroll
                for (int qq = 0; qq < 4; ++qq) {
                    const int q = (qq + rot) & 3;
                    const float4 v = ((const float4*)votes)[(idx << 2) | q];
                    float4 u;
                    u.x = fmaf(v.x, A4[qq].x, B4[qq].x);
                    u.y = fmaf(v.y, A4[qq].y, B4[qq].y);
                    u.z = fmaf(v.z, A4[qq].z, B4[qq].z);
                    u.w = fmaf(v.w, A4[qq].w, B4[qq].w);
                    s4.x = fmaf(v.x, u.x, s4.x);
                    s4.y = fmaf(v.y, u.y, s4.y);
                    s4.z = fmaf(v.z, u.z, s4.z);
                    s4.w = fmaf(v.w, u.w, s4.w);
                }
                rr[idx] = C - ((s4.x + s4.y) + (s4.z + s4.w));
            }
        }
        __syncthreads();

        // ---- softmax over o (base 2) per input capsule, scaled by acts[i] ----
        if (t < ICAP) {
            float4 z[4];
            #pragma unroll
            for (int qq = 0; qq < 4; ++qq) {
                const int q = (qq + rot) & 3;
                z[qq] = ((const float4*)rr)[(t << 2) | q];
            }
            float mx = -3.4e38f;
            #pragma unroll
            for (int qq = 0; qq < 4; ++qq)
                mx = fmaxf(mx, fmaxf(fmaxf(z[qq].x, z[qq].y), fmaxf(z[qq].z, z[qq].w)));
            float ss = 0.f;
            #pragma unroll
            for (int qq = 0; qq < 4; ++qq) {
                z[qq].x = exp2f(z[qq].x - mx); ss += z[qq].x;
                z[qq].y = exp2f(z[qq].y - mx); ss += z[qq].y;
                z[qq].z = exp2f(z[qq].z - mx); ss += z[qq].z;
                z[qq].w = exp2f(z[qq].w - mx); ss += z[qq].w;
            }
            const float scale = acts[t] / ss;    // fold acts into rr
            #pragma unroll
            for (int qq = 0; qq < 4; ++qq) {
                const int q = (qq + rot) & 3;
                float4 zz = z[qq];
                zz.x *= scale; zz.y *= scale; zz.z *= scale; zz.w *= scale;
                ((float4*)rr)[(t << 2) | q] = zz;
            }
        }
        __syncthreads();
    }
}

extern "C" void kernel_launch(void* const* d_in, const int* in_sizes, int n_in,
                              void* d_out, int out_size) {
    const float* pose_in = (const float*)d_in[0];
    const float* act_in  = (const float*)d_in[1];
    const float* w       = (const float*)d_in[2];
    const float* beta_v  = (const float*)d_in[3];
    const float* beta_a  = (const float*)d_in[4];
    float* out = (float*)d_out;

    cudaFuncSetAttribute(caps_em_kernel,
                         cudaFuncAttributeMaxDynamicSharedMemorySize, SMEM_BYTES);
    caps_em_kernel<<<NPOS, 512, SMEM_BYTES>>>(pose_in, act_in, w, beta_v, beta_a, out);
}